// round 7
// baseline (speedup 1.0000x reference)
#include <cuda_runtime.h>

#define BB   2
#define TT   2048
#define HIDD 2048
#define NH   16
#define NKV  4
#define HD   128
#define MR   (BB*TT)   // 4096

// ---------------- scratch (static device buffers; no allocation) ----------------
__device__ float g_q [(size_t)MR * NH  * HD];   // 33.5 MB
__device__ float g_k [(size_t)MR * NKV * HD];   //  8.4 MB
__device__ float g_v [(size_t)MR * NKV * HD];   //  8.4 MB
__device__ float g_ao[(size_t)MR * NH  * HD];   // 33.5 MB

// ---------------- SGEMM: C[M,N] = A[M,K] @ B[K,N], all row-major fp32 ----------
// BM=BN=128, BK=8, 256 threads, 8x8 microtile, float4 everywhere, reg prefetch.
__global__ __launch_bounds__(256, 2)
void sgemm128(const float* __restrict__ A, const float* __restrict__ B,
              float* __restrict__ C, int M, int N, int K)
{
    __shared__ float As[8][128];   // transposed A tile: As[k][m]
    __shared__ float Bs[8][128];   // Bs[k][n]

    const int tid = threadIdx.x;
    const int m0  = blockIdx.y * 128;
    const int n0  = blockIdx.x * 128;
    const int tx  = tid & 15;      // 0..15 -> n microtile
    const int ty  = tid >> 4;      // 0..15 -> m microtile

    // load mapping
    const int arow = tid >> 1;          // 0..127
    const int ak   = (tid & 1) << 2;    // 0 or 4
    const int brow = tid >> 5;          // 0..7
    const int bcol = (tid & 31) << 2;   // 0..124

    const float* Ap = A + (size_t)(m0 + arow) * K + ak;
    const float* Bp = B + (size_t)brow * N + n0 + bcol;

    float acc[8][8];
#pragma unroll
    for (int i = 0; i < 8; ++i)
#pragma unroll
        for (int j = 0; j < 8; ++j) acc[i][j] = 0.f;

    float4 av = *(const float4*)Ap;
    float4 bv = *(const float4*)Bp;

    for (int k0 = 0; k0 < K; k0 += 8) {
        As[ak + 0][arow] = av.x;
        As[ak + 1][arow] = av.y;
        As[ak + 2][arow] = av.z;
        As[ak + 3][arow] = av.w;
        *(float4*)&Bs[brow][bcol] = bv;
        __syncthreads();

        if (k0 + 8 < K) {   // prefetch next tile while computing
            av = *(const float4*)(Ap + k0 + 8);
            bv = *(const float4*)(Bp + (size_t)(k0 + 8) * N);
        }

#pragma unroll
        for (int kk = 0; kk < 8; ++kk) {
            float a[8], b[8];
            *(float4*)&a[0] = *(const float4*)&As[kk][ty * 8];
            *(float4*)&a[4] = *(const float4*)&As[kk][ty * 8 + 4];
            *(float4*)&b[0] = *(const float4*)&Bs[kk][tx * 8];
            *(float4*)&b[4] = *(const float4*)&Bs[kk][tx * 8 + 4];
#pragma unroll
            for (int i = 0; i < 8; ++i)
#pragma unroll
                for (int j = 0; j < 8; ++j)
                    acc[i][j] = fmaf(a[i], b[j], acc[i][j]);
        }
        __syncthreads();
    }

#pragma unroll
    for (int i = 0; i < 8; ++i) {
        float* cp = C + (size_t)(m0 + ty * 8 + i) * N + n0 + tx * 8;
        *(float4*)(cp)     = make_float4(acc[i][0], acc[i][1], acc[i][2], acc[i][3]);
        *(float4*)(cp + 4) = make_float4(acc[i][4], acc[i][5], acc[i][6], acc[i][7]);
    }
}

// ---------------- RoPE (in-place on q and k) -----------------------------------
// out[d]    = t[d]*cos[d]    - t[d+64]*sin[d]       (d < 64)
// out[d+64] = t[d+64]*cos[d+64] + t[d]*sin[d+64]
__global__ void rope_kernel(float* __restrict__ q, float* __restrict__ k,
                            const float* __restrict__ cosb,
                            const float* __restrict__ sinb)
{
    const int qpairs = MR * NH  * 64;   // 4,194,304
    const int kpairs = MR * NKV * 64;   // 1,048,576
    int idx = blockIdx.x * blockDim.x + threadIdx.x;

    if (idx < qpairs) {
        int d = idx & 63;
        int h = (idx >> 6) & (NH - 1);
        int m = idx >> 10;              // / (64*16)
        int t = m & (TT - 1);
        float c1 = cosb[t * HD + d],      s1 = sinb[t * HD + d];
        float c2 = cosb[t * HD + d + 64], s2 = sinb[t * HD + d + 64];
        float* base = q + (size_t)m * (NH * HD) + h * HD;
        float a  = base[d];
        float bb = base[d + 64];
        base[d]      = a * c1 - bb * s1;
        base[d + 64] = bb * c2 + a * s2;
    } else if (idx < qpairs + kpairs) {
        int j = idx - qpairs;
        int d = j & 63;
        int h = (j >> 6) & (NKV - 1);
        int m = j >> 8;                 // / (64*4)
        int t = m & (TT - 1);
        float c1 = cosb[t * HD + d],      s1 = sinb[t * HD + d];
        float c2 = cosb[t * HD + d + 64], s2 = sinb[t * HD + d + 64];
        float* base = k + (size_t)m * (NKV * HD) + h * HD;
        float a  = base[d];
        float bb = base[d + 64];
        base[d]      = a * c1 - bb * s1;
        base[d + 64] = bb * c2 + a * s2;
    }
}

// ---------------- Flash attention (causal, GQA 16q/4kv heads) ------------------
// BQ = BK = 64, 256 threads. Score microtile 4x4 (rows ty*4+i, cols tx+16*j).
// O microtile 4x8 (rows ty*4+i, cols tx*8..). Online softmax, P via smem.
#define QSTR 132            // padded row stride (floats) for Q/K/V tiles
#define PSTR 68             // padded row stride for P tile
#define FA_SMEM_FLOATS (3 * 64 * QSTR + 64 * PSTR)   // 29,696 floats
#define FA_SMEM_BYTES  (FA_SMEM_FLOATS * 4)          // 118,784 B

__global__ __launch_bounds__(256, 1)
void flash_attn(const float* __restrict__ q, const float* __restrict__ k,
                const float* __restrict__ v, float* __restrict__ o)
{
    extern __shared__ float sm[];
    float* Qs = sm;
    float* Ks = sm + 64 * QSTR;
    float* Vs = sm + 2 * 64 * QSTR;
    float* Ps = sm + 3 * 64 * QSTR;

    const int qb  = blockIdx.x;        // 0..31
    const int h   = blockIdx.y;        // 0..15
    const int b   = blockIdx.z;        // 0..1
    const int kvh = h >> 2;            // GQA: 4 q-heads per kv-head
    const int q0  = qb * 64;
    const int tid = threadIdx.x;
    const int tx  = tid & 15;
    const int ty  = tid >> 4;
    const float scale = 0.08838834764831845f;   // 1/sqrt(128)

    // Load + pre-scale Q tile (64 rows x 128)
    const float* qbase = q + ((size_t)(b * TT + q0)) * (NH * HD) + (size_t)h * HD;
#pragma unroll
    for (int it = 0; it < 8; ++it) {
        int p   = tid + it * 256;       // float4 index 0..2047
        int row = p >> 5;
        int c4  = (p & 31) << 2;
        float4 val = *(const float4*)(qbase + (size_t)row * (NH * HD) + c4);
        val.x *= scale; val.y *= scale; val.z *= scale; val.w *= scale;
        *(float4*)(Qs + row * QSTR + c4) = val;
    }

    float m_i[4], l_i[4], oacc[4][8];
#pragma unroll
    for (int i = 0; i < 4; ++i) {
        m_i[i] = -3.0e38f;
        l_i[i] = 0.f;
#pragma unroll
        for (int c = 0; c < 8; ++c) oacc[i][c] = 0.f;
    }

    const float* kbase = k + ((size_t)(b * TT)) * (NKV * HD) + (size_t)kvh * HD;
    const float* vbase = v + ((size_t)(b * TT)) * (NKV * HD) + (size_t)kvh * HD;

    for (int kt = 0; kt <= qb; ++kt) {
        __syncthreads();                // protect Ks/Vs reuse from prior PV reads
#pragma unroll
        for (int it = 0; it < 8; ++it) {
            int p   = tid + it * 256;
            int row = p >> 5;
            int c4  = (p & 31) << 2;
            size_t g = (size_t)(kt * 64 + row) * (NKV * HD) + c4;
            *(float4*)(Ks + row * QSTR + c4) = *(const float4*)(kbase + g);
            *(float4*)(Vs + row * QSTR + c4) = *(const float4*)(vbase + g);
        }
        __syncthreads();

        // S = Q K^T ; rows ty*4+i, cols tx+16*j
        float s[4][4];
#pragma unroll
        for (int i = 0; i < 4; ++i)
#pragma unroll
            for (int j = 0; j < 4; ++j) s[i][j] = 0.f;

#pragma unroll 4
        for (int d = 0; d < HD; d += 4) {
            float4 qv[4], kv[4];
#pragma unroll
            for (int i = 0; i < 4; ++i)
                qv[i] = *(const float4*)(Qs + (ty * 4 + i) * QSTR + d);
#pragma unroll
            for (int j = 0; j < 4; ++j)
                kv[j] = *(const float4*)(Ks + (tx + 16 * j) * QSTR + d);
#pragma unroll
            for (int i = 0; i < 4; ++i)
#pragma unroll
                for (int j = 0; j < 4; ++j) {
                    s[i][j] = fmaf(qv[i].x, kv[j].x, s[i][j]);
                    s[i][j] = fmaf(qv[i].y, kv[j].y, s[i][j]);
                    s[i][j] = fmaf(qv[i].z, kv[j].z, s[i][j]);
                    s[i][j] = fmaf(qv[i].w, kv[j].w, s[i][j]);
                }
        }

        // Causal mask (diagonal tile only)
        if (kt == qb) {
#pragma unroll
            for (int i = 0; i < 4; ++i)
#pragma unroll
                for (int j = 0; j < 4; ++j)
                    if (tx + 16 * j > ty * 4 + i) s[i][j] = -3.0e38f;
        }

        // Online softmax; row group = 16 lanes sharing ty
#pragma unroll
        for (int i = 0; i < 4; ++i) {
            float mx = fmaxf(fmaxf(s[i][0], s[i][1]), fmaxf(s[i][2], s[i][3]));
#pragma unroll
            for (int w = 1; w < 16; w <<= 1)
                mx = fmaxf(mx, __shfl_xor_sync(0xffffffffu, mx, w));
            float mn = fmaxf(m_i[i], mx);
            float p0 = __expf(s[i][0] - mn);
            float p1 = __expf(s[i][1] - mn);
            float p2 = __expf(s[i][2] - mn);
            float p3 = __expf(s[i][3] - mn);
            float rsum = p0 + p1 + p2 + p3;
#pragma unroll
            for (int w = 1; w < 16; w <<= 1)
                rsum += __shfl_xor_sync(0xffffffffu, rsum, w);
            float sc = __expf(m_i[i] - mn);
            l_i[i] = l_i[i] * sc + rsum;
            m_i[i] = mn;
#pragma unroll
            for (int c = 0; c < 8; ++c) oacc[i][c] *= sc;
            int prow = (ty * 4 + i) * PSTR + tx;
            Ps[prow +  0] = p0;
            Ps[prow + 16] = p1;
            Ps[prow + 32] = p2;
            Ps[prow + 48] = p3;
        }
        __syncwarp();   // P rows are produced & consumed within the same warp

        // O += P @ V ; rows ty*4+i, cols tx*8..tx*8+7
#pragma unroll 2
        for (int j = 0; j < 64; ++j) {
            float pr[4];
#pragma unroll
            for (int i = 0; i < 4; ++i) pr[i] = Ps[(ty * 4 + i) * PSTR + j];
            float4 v0 = *(const float4*)(Vs + j * QSTR + tx * 8);
            float4 v1 = *(const float4*)(Vs + j * QSTR + tx * 8 + 4);
#pragma unroll
            for (int i = 0; i < 4; ++i) {
                oacc[i][0] = fmaf(pr[i], v0.x, oacc[i][0]);
                oacc[i][1] = fmaf(pr[i], v0.y, oacc[i][1]);
                oacc[i][2] = fmaf(pr[i], v0.z, oacc[i][2]);
                oacc[i][3] = fmaf(pr[i], v0.w, oacc[i][3]);
                oacc[i][4] = fmaf(pr[i], v1.x, oacc[i][4]);
                oacc[i][5] = fmaf(pr[i], v1.y, oacc[i][5]);
                oacc[i][6] = fmaf(pr[i], v1.z, oacc[i][6]);
                oacc[i][7] = fmaf(pr[i], v1.w, oacc[i][7]);
            }
        }
    }

    // Epilogue: normalize and write (b, q, h, d) layout
    float* obase = o + ((size_t)(b * TT + q0)) * (NH * HD) + (size_t)h * HD;
#pragma unroll
    for (int i = 0; i < 4; ++i) {
        float inv = 1.0f / l_i[i];
        float* op = obase + (size_t)(ty * 4 + i) * (NH * HD) + tx * 8;
        *(float4*)(op)     = make_float4(oacc[i][0] * inv, oacc[i][1] * inv,
                                         oacc[i][2] * inv, oacc[i][3] * inv);
        *(float4*)(op + 4) = make_float4(oacc[i][4] * inv, oacc[i][5] * inv,
                                         oacc[i][6] * inv, oacc[i][7] * inv);
    }
}

// ---------------- launch --------------------------------------------------------
extern "C" void kernel_launch(void* const* d_in, const int* in_sizes, int n_in,
                              void* d_out, int out_size)
{
    (void)in_sizes; (void)n_in; (void)out_size;
    const float* x   = (const float*)d_in[0];
    const float* rc  = (const float*)d_in[1];
    const float* rsn = (const float*)d_in[2];
    const float* Wq  = (const float*)d_in[3];
    const float* Wk  = (const float*)d_in[4];
    const float* Wv  = (const float*)d_in[5];
    const float* Wo  = (const float*)d_in[6];
    float* out = (float*)d_out;

    float *gq, *gk, *gv, *gao;
    cudaGetSymbolAddress((void**)&gq,  g_q);
    cudaGetSymbolAddress((void**)&gk,  g_k);
    cudaGetSymbolAddress((void**)&gv,  g_v);
    cudaGetSymbolAddress((void**)&gao, g_ao);

    dim3 blk(256);

    // QKV projections
    sgemm128<<<dim3((NH  * HD) / 128, MR / 128), blk>>>(x, Wq, gq, MR, NH  * HD, HIDD);
    sgemm128<<<dim3((NKV * HD) / 128, MR / 128), blk>>>(x, Wk, gk, MR, NKV * HD, HIDD);
    sgemm128<<<dim3((NKV * HD) / 128, MR / 128), blk>>>(x, Wv, gv, MR, NKV * HD, HIDD);

    // RoPE on q and k
    const int totalPairs = MR * NH * 64 + MR * NKV * 64;
    rope_kernel<<<(totalPairs + 255) / 256, 256>>>(gq, gk, rc, rsn);

    // Flash attention
    cudaFuncSetAttribute(flash_attn, cudaFuncAttributeMaxDynamicSharedMemorySize,
                         FA_SMEM_BYTES);
    flash_attn<<<dim3(TT / 64, NH, BB), blk, FA_SMEM_BYTES>>>(gq, gk, gv, gao);

    // Output projection
    sgemm128<<<dim3((NH * HD) / 128, MR / 128), blk>>>(gao, Wo, out, MR, NH * HD, HIDD);
}